// round 11
// baseline (speedup 1.0000x reference)
#include <cuda_runtime.h>
#include <cuda_bf16.h>
#include <cstdint>

#define B_   256
#define T_   10
#define BT_  2560
#define HW_  49
#define VD_  512
#define AD_  128
#define HD_  256

// ---------------------------------------------------------------------------
// Scratch (__device__ globals — allocation-free)
// ---------------------------------------------------------------------------
__device__ float g_aq1[BT_ * VD_];
__device__ float g_aq2[BT_ * HD_];
__device__ float g_m1 [BT_ * VD_];
__device__ float g_scale[BT_ * VD_];

// Pre-split bf16 weight images, UNPADDED 128B rows:
// [n_chunk][k_chunk(8)][128 n-rows][64 k]
__device__ __align__(16) __nv_bfloat16 g_W1h[4 * 8 * 128 * 64];
__device__ __align__(16) __nv_bfloat16 g_W1l[4 * 8 * 128 * 64];
__device__ __align__(16) __nv_bfloat16 g_W2h[2 * 8 * 128 * 64];
__device__ __align__(16) __nv_bfloat16 g_W2l[2 * 8 * 128 * 64];

// Transposed packed fp32 weights for k3: WbT4[k4][j] / WcT4[k4][c]
__device__ __align__(16) float4 g_WbT4[128 * 256];
__device__ __align__(16) float4 g_WcT4[64 * 512];

#define CHUNK_ELEMS (128 * 64)           // 8192 bf16 = 16384 B per image chunk
#define ROWB 144                         // smem row stride (72 bf16)
#define MT_STRIDE (16 * ROWB)

// SMEM layout (dynamic, 92160 B): A_h@0 (9216) A_l@9216 (9216)
//                                 W_h@18432 (36864) W_l@55296 (36864)
#define SM_AL 9216
#define SM_WH 18432
#define SM_WL 55296
#define SMEM_BYTES 92160

// ---------------------------------------------------------------------------
// Helpers (plain sm_103-safe PTX only)
// ---------------------------------------------------------------------------
__device__ __forceinline__ uint32_t smem_u32(const void* p) {
    uint32_t a;
    asm("{ .reg .u64 t; cvta.to.shared.u64 t, %1; cvt.u32.u64 %0, t; }"
        : "=r"(a) : "l"(p));
    return a;
}
__device__ __forceinline__ void ldmx4(uint32_t addr, uint32_t r[4]) {
    asm volatile("ldmatrix.sync.aligned.m8n8.x4.shared.b16 {%0,%1,%2,%3}, [%4];"
                 : "=r"(r[0]), "=r"(r[1]), "=r"(r[2]), "=r"(r[3]) : "r"(addr));
}
__device__ __forceinline__ void mma_bf16(float d[4], const uint32_t a[4],
                                         uint32_t b0, uint32_t b1) {
    asm volatile(
        "mma.sync.aligned.m16n8k16.row.col.f32.bf16.bf16.f32 "
        "{%0,%1,%2,%3},{%4,%5,%6,%7},{%8,%9},{%0,%1,%2,%3};"
        : "+f"(d[0]), "+f"(d[1]), "+f"(d[2]), "+f"(d[3])
        : "r"(a[0]), "r"(a[1]), "r"(a[2]), "r"(a[3]), "r"(b0), "r"(b1));
}
__device__ __forceinline__ void cp16(uint32_t dst, const void* src) {
    asm volatile("cp.async.cg.shared.global [%0], [%1], 16;" :: "r"(dst), "l"(src));
}
__device__ __forceinline__ void cp_commit_wait() {
    asm volatile("cp.async.commit_group;" ::: "memory");
    asm volatile("cp.async.wait_group 0;" ::: "memory");
}

__device__ __forceinline__ void split_store(char* Ah, char* Al, int r, int q,
                                            float x0, float x1, float x2, float x3) {
    __nv_bfloat16 h0 = __float2bfloat16(x0), h1 = __float2bfloat16(x1);
    __nv_bfloat16 h2 = __float2bfloat16(x2), h3 = __float2bfloat16(x3);
    __nv_bfloat16 l0 = __float2bfloat16(x0 - __bfloat162float(h0));
    __nv_bfloat16 l1 = __float2bfloat16(x1 - __bfloat162float(h1));
    __nv_bfloat16 l2 = __float2bfloat16(x2 - __bfloat162float(h2));
    __nv_bfloat16 l3 = __float2bfloat16(x3 - __bfloat162float(h3));
    __nv_bfloat162 p;
    char* dh = Ah + r * ROWB + q * 8;
    char* dl = Al + r * ROWB + q * 8;
    p.x = h0; p.y = h1; *(__nv_bfloat162*)dh = p;
    p.x = h2; p.y = h3; *(__nv_bfloat162*)(dh + 4) = p;
    p.x = l0; p.y = l1; *(__nv_bfloat162*)dl = p;
    p.x = l2; p.y = l3; *(__nv_bfloat162*)(dl + 4) = p;
}

// ---------------------------------------------------------------------------
// k0: split Wv1/Wv2 into bf16 hi/lo UNPADDED tile images
// ---------------------------------------------------------------------------
__global__ void __launch_bounds__(256)
k0_wconv(const float* __restrict__ Wv1, const float* __restrict__ Wv2)
{
    int idx = blockIdx.x * 256 + threadIdx.x;
    if (idx < 512 * 512) {
        int c = idx >> 9, k = idx & 511;
        float v = Wv1[idx];
        __nv_bfloat16 h = __float2bfloat16(v);
        __nv_bfloat16 l = __float2bfloat16(v - __bfloat162float(h));
        int nc = c >> 7, nl = c & 127, kc = k >> 6, kk = k & 63;
        size_t d = ((size_t)(nc * 8 + kc) * 128 + nl) * 64 + kk;
        g_W1h[d] = h; g_W1l[d] = l;
    } else if (idx < 512 * 512 + 256 * 512) {
        int e = idx - 512 * 512;
        int j = e >> 9, k = e & 511;
        float v = Wv2[e];
        __nv_bfloat16 h = __float2bfloat16(v);
        __nv_bfloat16 l = __float2bfloat16(v - __bfloat162float(h));
        int nc = j >> 7, nl = j & 127, kc = k >> 6, kk = k & 63;
        size_t d = ((size_t)(nc * 8 + kc) * 128 + nl) * 64 + kk;
        g_W2h[d] = h; g_W2l[d] = l;
    }
}

// ---------------------------------------------------------------------------
// kt: build transposed packed fp32 weights for k3
// ---------------------------------------------------------------------------
__global__ void __launch_bounds__(256)
kt_trans(const float* __restrict__ Wb, const float* __restrict__ Wc)
{
    int idx = blockIdx.x * 256 + threadIdx.x;
    if (idx < 128 * 256) {
        int k4 = idx >> 8, j = idx & 255;
        const float* s = Wb + (size_t)j * VD_ + k4 * 4;
        g_WbT4[idx] = make_float4(s[0], s[1], s[2], s[3]);
    } else if (idx < 128 * 256 + 64 * 512) {
        int e = idx - 128 * 256;
        int k4 = e >> 9, c = e & 511;
        const float* s = Wc + (size_t)c * HD_ + k4 * 4;
        g_WcT4[e] = make_float4(s[0], s[1], s[2], s[3]);
    }
}

// ---------------------------------------------------------------------------
// k1: audio features (proven, unchanged)
// ---------------------------------------------------------------------------
__global__ void __launch_bounds__(256)
k1_audio(const float* __restrict__ audio,
         const float* __restrict__ Wa1, const float* __restrict__ ba1,
         const float* __restrict__ Wa2, const float* __restrict__ ba2)
{
    __shared__ __align__(16) float af[32][AD_];
    const int tid = threadIdx.x;
    const int bt0 = blockIdx.x * 32;

    for (int idx = tid; idx < 32 * AD_; idx += 256) {
        int i = idx >> 7, k = idx & 127;
        int bt = bt0 + i;
        int b = bt / T_, t = bt - b * T_;
        af[i][k] = audio[((size_t)t * B_ + b) * AD_ + k];
    }
    __syncthreads();

    for (int c = tid; c < VD_; c += 256) {
        const float4* w4 = (const float4*)(Wa1 + (size_t)c * AD_);
        float acc[32];
#pragma unroll
        for (int i = 0; i < 32; ++i) acc[i] = 0.f;
        for (int k4 = 0; k4 < AD_ / 4; ++k4) {
            float4 w = w4[k4];
#pragma unroll
            for (int i = 0; i < 32; ++i) {
                float4 v = *(const float4*)&af[i][k4 * 4];
                acc[i] += v.x * w.x + v.y * w.y + v.z * w.z + v.w * w.w;
            }
        }
        float bias = ba1[c];
#pragma unroll
        for (int i = 0; i < 32; ++i)
            g_aq1[(size_t)(bt0 + i) * VD_ + c] = fmaxf(acc[i] + bias, 0.f);
    }
    {
        int j = tid;
        const float4* w4 = (const float4*)(Wa2 + (size_t)j * AD_);
        float acc[32];
#pragma unroll
        for (int i = 0; i < 32; ++i) acc[i] = 0.f;
        for (int k4 = 0; k4 < AD_ / 4; ++k4) {
            float4 w = w4[k4];
#pragma unroll
            for (int i = 0; i < 32; ++i) {
                float4 v = *(const float4*)&af[i][k4 * 4];
                acc[i] += v.x * w.x + v.y * w.y + v.z * w.z + v.w * w.w;
            }
        }
        float bias = ba2[j];
#pragma unroll
        for (int i = 0; i < 32; ++i)
            g_aq2[(size_t)(bt0 + i) * HD_ + j] = fmaxf(acc[i] + bias, 0.f);
    }
}

// ---------------------------------------------------------------------------
// GEMM mainloop: M=64 (one clip), N=256, K chunks of 64, single buffer,
// 2 CTAs/SM. (R10-proven; W copies now re-stride 128B global rows -> 144B.)
// ---------------------------------------------------------------------------
__device__ __forceinline__ void gemm_mainloop(
    float acc[2][8][4], char* sm, uint32_t aBase,
    const float* __restrict__ video, const float* scale /*nullptr or clip row*/,
    const __nv_bfloat16* wH0, const __nv_bfloat16* wL0,
    const __nv_bfloat16* wH1, const __nv_bfloat16* wL1,
    int bt, int tid, int lane, int wm, int wn)
{
    char* A_h = sm;
    char* A_l = sm + SM_AL;

    // zero pad rows 49..63 of A (hi+lo), once
    for (int i = tid; i < 540; i += 256) {
        int r = 49 + i / 36, o = (i % 36) * 4;
        *(uint32_t*)(A_h + r * ROWB + o) = 0u;
        *(uint32_t*)(A_l + r * ROWB + o) = 0u;
    }

    const uint32_t pAh = aBase + (uint32_t)((wm * 32 + (lane & 15)) * ROWB
                        + ((lane >> 4) & 1) * 16);
    const uint32_t pAl = pAh + SM_AL;
    const uint32_t pBh = aBase + SM_WH
                        + (uint32_t)((wn * 64 + (lane & 7) + ((lane >> 4) & 1) * 8) * ROWB
                        + ((lane >> 3) & 1) * 16);
    const uint32_t pBl = pBh + (SM_WL - SM_WH);

    for (int kc = 0; kc < 8; ++kc) {
        __syncthreads();   // prior chunk's ldmatrix reads done before overwrite
        // W chunk: 4 unpadded images (16384B each), re-strided to 144B rows
        {
            const char* sH0 = (const char*)(wH0 + (size_t)kc * CHUNK_ELEMS);
            const char* sH1 = (const char*)(wH1 + (size_t)kc * CHUNK_ELEMS);
            const char* sL0 = (const char*)(wL0 + (size_t)kc * CHUNK_ELEMS);
            const char* sL1 = (const char*)(wL1 + (size_t)kc * CHUNK_ELEMS);
            for (int i = tid; i < 1024; i += 256) {
                int r = i >> 3, q = i & 7;
                uint32_t dof = (uint32_t)(r * ROWB + q * 16);
                int sof = r * 128 + q * 16;
                cp16(aBase + SM_WH + dof,         sH0 + sof);
                cp16(aBase + SM_WH + 18432 + dof, sH1 + sof);
                cp16(aBase + SM_WL + dof,         sL0 + sof);
                cp16(aBase + SM_WL + 18432 + dof, sL1 + sof);
            }
        }
        // A chunk: convert 49 x 64 fp32 -> bf16 hi/lo (optionally x scale)
        for (int idx = tid; idx < 49 * 16; idx += 256) {
            int r = idx >> 4, q = idx & 15;
            float4 v = *(const float4*)(video +
                ((size_t)bt * HW_ + r) * VD_ + kc * 64 + q * 4);
            if (scale) {
                float4 s = *(const float4*)(scale + kc * 64 + q * 4);
                v.x *= s.x; v.y *= s.y; v.z *= s.z; v.w *= s.w;
            }
            split_store(A_h, A_l, r, q, v.x, v.y, v.z, v.w);
        }
        cp_commit_wait();
        __syncthreads();

        // MMA on chunk kc
#pragma unroll
        for (int ks = 0; ks < 4; ++ks) {
            uint32_t ah[2][4], al[2][4];
#pragma unroll
            for (int mt = 0; mt < 2; ++mt) {
                ldmx4(pAh + mt * MT_STRIDE + ks * 32, ah[mt]);
                ldmx4(pAl + mt * MT_STRIDE + ks * 32, al[mt]);
            }
#pragma unroll
            for (int np = 0; np < 4; ++np) {
                uint32_t bh4[4], bl4[4];
                ldmx4(pBh + np * MT_STRIDE + ks * 32, bh4);
                ldmx4(pBl + np * MT_STRIDE + ks * 32, bl4);
#pragma unroll
                for (int mt = 0; mt < 2; ++mt)
#pragma unroll
                    for (int sub = 0; sub < 2; ++sub) {
                        int nt = np * 2 + sub, s = sub * 2;
                        mma_bf16(acc[mt][nt], ah[mt], bh4[s], bh4[s + 1]);
                        mma_bf16(acc[mt][nt], al[mt], bh4[s], bh4[s + 1]);
                        mma_bf16(acc[mt][nt], ah[mt], bl4[s], bl4[s + 1]);
                    }
            }
        }
    }
    __syncthreads();   // smem free for epilogue reuse
}

// ---------------------------------------------------------------------------
// g1: GEMM1 + relu + hw-mean + x aq1/49 -> g_m1.  grid = (2 n-halves, 2560)
// ---------------------------------------------------------------------------
__global__ void __launch_bounds__(256, 2)
g1_mma(const float* __restrict__ video, const float* __restrict__ bv1)
{
    extern __shared__ char sm[];
    const int tid = threadIdx.x, wid = tid >> 5, lane = tid & 31;
    const int wm = wid >> 2, wn = wid & 3;
    const int nh = blockIdx.x, bt = blockIdx.y;
    const uint32_t aBase = smem_u32(sm);

    float acc[2][8][4];
#pragma unroll
    for (int a = 0; a < 2; ++a)
#pragma unroll
        for (int b = 0; b < 8; ++b)
#pragma unroll
            for (int c = 0; c < 4; ++c) acc[a][b][c] = 0.f;

    gemm_mainloop(acc, sm, aBase, video, nullptr,
                  g_W1h + (size_t)(nh * 2)     * 8 * CHUNK_ELEMS,
                  g_W1l + (size_t)(nh * 2)     * 8 * CHUNK_ELEMS,
                  g_W1h + (size_t)(nh * 2 + 1) * 8 * CHUNK_ELEMS,
                  g_W1l + (size_t)(nh * 2 + 1) * 8 * CHUNK_ELEMS,
                  bt, tid, lane, wm, wn);

    // stage relu(D + bias) into smem [64][260]
    float* stage = (float*)sm;
#pragma unroll
    for (int mt = 0; mt < 2; ++mt)
#pragma unroll
        for (int nt = 0; nt < 8; ++nt) {
            int r0 = wm * 32 + mt * 16 + (lane >> 2);
            int c0 = wn * 64 + nt * 8 + (lane & 3) * 2;
            float b0 = bv1[nh * 256 + c0], b1 = bv1[nh * 256 + c0 + 1];
            stage[r0 * 260 + c0]           = fmaxf(acc[mt][nt][0] + b0, 0.f);
            stage[r0 * 260 + c0 + 1]       = fmaxf(acc[mt][nt][1] + b1, 0.f);
            stage[(r0 + 8) * 260 + c0]     = fmaxf(acc[mt][nt][2] + b0, 0.f);
            stage[(r0 + 8) * 260 + c0 + 1] = fmaxf(acc[mt][nt][3] + b1, 0.f);
        }
    __syncthreads();

    {
        float s = 0.f;
#pragma unroll
        for (int h = 0; h < HW_; ++h) s += stage[h * 260 + tid];
        int c = nh * 256 + tid;
        g_m1[(size_t)bt * VD_ + c] =
            g_aq1[(size_t)bt * VD_ + c] * s * (1.f / 49.f);
    }
}

// ---------------------------------------------------------------------------
// k3: channel-attention MLP with transposed coalesced weights, 16 clips/block
// ---------------------------------------------------------------------------
__global__ void __launch_bounds__(256)
k3_catt(const float* __restrict__ bb, const float* __restrict__ bc)
{
    __shared__ __align__(16) float4 m1s4[16 * 128];   // [clip][k4]
    __shared__ __align__(16) float t1s[16][HD_];
    const int tid = threadIdx.x;
    const int bt0 = blockIdx.x * 16;

    {
        const float4* src = (const float4*)(g_m1 + (size_t)bt0 * VD_);
        for (int i = tid; i < 16 * 128; i += 256) m1s4[i] = src[i];
    }
    __syncthreads();

    // stage1: thread j computes t1[i][j] for 16 clips; coalesced WbT4 reads
    {
        const int j = tid;
        float acc[16];
#pragma unroll
        for (int i = 0; i < 16; ++i) acc[i] = 0.f;
        for (int k4 = 0; k4 < 128; ++k4) {
            float4 w = g_WbT4[k4 * 256 + j];
#pragma unroll
            for (int i = 0; i < 16; ++i) {
                float4 v = m1s4[i * 128 + k4];
                acc[i] += v.x * w.x + v.y * w.y + v.z * w.z + v.w * w.w;
            }
        }
        float bias = bb[j];
#pragma unroll
        for (int i = 0; i < 16; ++i) t1s[i][j] = fmaxf(acc[i] + bias, 0.f);
    }
    __syncthreads();

    // stage2: thread handles c = tid and tid+256; coalesced WcT4 reads
    {
        const int c0 = tid, c1 = tid + 256;
        float acc0[16], acc1[16];
#pragma unroll
        for (int i = 0; i < 16; ++i) { acc0[i] = 0.f; acc1[i] = 0.f; }
        for (int k4 = 0; k4 < 64; ++k4) {
            float4 w0 = g_WcT4[k4 * 512 + c0];
            float4 w1 = g_WcT4[k4 * 512 + c1];
#pragma unroll
            for (int i = 0; i < 16; ++i) {
                float4 v = *(const float4*)&t1s[i][k4 * 4];
                acc0[i] += v.x * w0.x + v.y * w0.y + v.z * w0.z + v.w * w0.w;
                acc1[i] += v.x * w1.x + v.y * w1.y + v.z * w1.z + v.w * w1.w;
            }
        }
        float b0 = bc[c0], b1 = bc[c1];
#pragma unroll
        for (int i = 0; i < 16; ++i) {
            float x0 = acc0[i] + b0, x1 = acc1[i] + b1;
            g_scale[(size_t)(bt0 + i) * VD_ + c0] = 1.f + 1.f / (1.f + expf(-x0));
            g_scale[(size_t)(bt0 + i) * VD_ + c1] = 1.f + 1.f / (1.f + expf(-x1));
        }
    }
}

// ---------------------------------------------------------------------------
// g2: GEMM2 + relu x (aq2*Ws) row sums + tanh/softmax + output (fully fused)
// grid = 2560
// ---------------------------------------------------------------------------
__global__ void __launch_bounds__(256, 2)
g2_mma(const float* __restrict__ video, const float* __restrict__ bv2,
       const float* __restrict__ Ws, const float* __restrict__ bs,
       float* __restrict__ out)
{
    extern __shared__ char sm[];
    __shared__ float u_s[256];
    __shared__ float part[64];
    __shared__ float swt[64];
    __shared__ float smx, sdn;
    const int tid = threadIdx.x, wid = tid >> 5, lane = tid & 31;
    const int wm = wid >> 2, wn = wid & 3;
    const int bt = blockIdx.x;
    const uint32_t aBase = smem_u32(sm);

    u_s[tid] = g_aq2[(size_t)bt * HD_ + tid] * Ws[tid];
    if (tid < 64) part[tid] = 0.f;

    float acc[2][8][4];
#pragma unroll
    for (int a = 0; a < 2; ++a)
#pragma unroll
        for (int b = 0; b < 8; ++b)
#pragma unroll
            for (int c = 0; c < 4; ++c) acc[a][b][c] = 0.f;

    gemm_mainloop(acc, sm, aBase, video, g_scale + (size_t)bt * VD_,
                  g_W2h, g_W2l,
                  g_W2h + (size_t)8 * CHUNK_ELEMS,
                  g_W2l + (size_t)8 * CHUNK_ELEMS,
                  bt, tid, lane, wm, wn);

    // row sums: sum_j relu(D + bv2[j]) * u[j]
#pragma unroll
    for (int mt = 0; mt < 2; ++mt) {
        int r0 = wm * 32 + mt * 16 + (lane >> 2);
        float s0 = 0.f, s1 = 0.f;
#pragma unroll
        for (int nt = 0; nt < 8; ++nt) {
            int c0 = wn * 64 + nt * 8 + (lane & 3) * 2;
            float b0 = bv2[c0], b1 = bv2[c0 + 1];
            float u0 = u_s[c0], u1 = u_s[c0 + 1];
            s0 += fmaxf(acc[mt][nt][0] + b0, 0.f) * u0
                + fmaxf(acc[mt][nt][1] + b1, 0.f) * u1;
            s1 += fmaxf(acc[mt][nt][2] + b0, 0.f) * u0
                + fmaxf(acc[mt][nt][3] + b1, 0.f) * u1;
        }
        s0 += __shfl_xor_sync(0xffffffffu, s0, 1);
        s0 += __shfl_xor_sync(0xffffffffu, s0, 2);
        s1 += __shfl_xor_sync(0xffffffffu, s1, 1);
        s1 += __shfl_xor_sync(0xffffffffu, s1, 2);
        if ((lane & 3) == 0) {
            atomicAdd(&part[r0], s0);
            atomicAdd(&part[r0 + 8], s1);
        }
    }
    __syncthreads();

    // fused k5: tanh + softmax + output contraction
    if (tid < HW_) swt[tid] = tanhf(part[tid] + bs[0]);
    __syncthreads();
    if (tid == 0) {
        float mx = -1e30f;
        for (int h = 0; h < HW_; ++h) mx = fmaxf(mx, swt[h]);
        float den = 0.f;
        for (int h = 0; h < HW_; ++h) den += expf(swt[h] - mx);
        smx = mx; sdn = den;
    }
    __syncthreads();
    if (tid < HW_) swt[tid] = expf(swt[tid] - smx) / sdn;
    __syncthreads();

    for (int c = tid; c < VD_; c += 256) {
        float a = 0.f;
#pragma unroll 7
        for (int h = 0; h < HW_; ++h)
            a += swt[h] * video[((size_t)bt * HW_ + h) * VD_ + c];
        out[(size_t)bt * VD_ + c] = a * g_scale[(size_t)bt * VD_ + c];
    }
}

// ---------------------------------------------------------------------------
// Launch
// ---------------------------------------------------------------------------
extern "C" void kernel_launch(void* const* d_in, const int* in_sizes, int n_in,
                              void* d_out, int out_size)
{
    const float* video = (const float*)d_in[0];
    const float* audio = (const float*)d_in[1];
    const float* Wv1   = (const float*)d_in[2];
    const float* bv1   = (const float*)d_in[3];
    const float* Wa1   = (const float*)d_in[4];
    const float* ba1   = (const float*)d_in[5];
    const float* Wb    = (const float*)d_in[6];
    const float* bb    = (const float*)d_in[7];
    const float* Wc    = (const float*)d_in[8];
    const float* bc    = (const float*)d_in[9];
    const float* Wv2   = (const float*)d_in[10];
    const float* bv2   = (const float*)d_in[11];
    const float* Wa2   = (const float*)d_in[12];
    const float* ba2   = (const float*)d_in[13];
    const float* Ws    = (const float*)d_in[14];
    const float* bs    = (const float*)d_in[15];
    float* out = (float*)d_out;

    cudaFuncSetAttribute(g1_mma, cudaFuncAttributeMaxDynamicSharedMemorySize, SMEM_BYTES);
    cudaFuncSetAttribute(g2_mma, cudaFuncAttributeMaxDynamicSharedMemorySize, SMEM_BYTES);

    k0_wconv<<<1536, 256>>>(Wv1, Wv2);
    kt_trans<<<256, 256>>>(Wb, Wc);
    k1_audio<<<BT_ / 32, 256>>>(audio, Wa1, ba1, Wa2, ba2);
    g1_mma<<<dim3(2, BT_), 256, SMEM_BYTES>>>(video, bv1);
    k3_catt<<<BT_ / 16, 256>>>(bb, bc);
    g2_mma<<<BT_, 256, SMEM_BYTES>>>(video, bv2, Ws, bs, out);
}

// round 12
// speedup vs baseline: 1.1205x; 1.1205x over previous
#include <cuda_runtime.h>
#include <cuda_bf16.h>
#include <cstdint>

#define B_   256
#define T_   10
#define BT_  2560
#define HW_  49
#define VD_  512
#define AD_  128
#define HD_  256

// ---------------------------------------------------------------------------
// Scratch (__device__ globals — allocation-free)
// ---------------------------------------------------------------------------
__device__ float g_aq1[BT_ * VD_];
__device__ float g_aq2[BT_ * HD_];
__device__ float g_m1 [BT_ * VD_];
__device__ float g_scale[BT_ * VD_];

// Pre-split bf16 weight images, K=32 chunks, unpadded 64B rows:
// [n_chunk][k_chunk(16)][128 n-rows][32 k]
__device__ __align__(16) __nv_bfloat16 g_W1h[4 * 16 * 128 * 32];
__device__ __align__(16) __nv_bfloat16 g_W1l[4 * 16 * 128 * 32];
__device__ __align__(16) __nv_bfloat16 g_W2h[2 * 16 * 128 * 32];
__device__ __align__(16) __nv_bfloat16 g_W2l[2 * 16 * 128 * 32];

// Transposed packed fp32 weights for k3
__device__ __align__(16) float4 g_WbT4[128 * 256];
__device__ __align__(16) float4 g_WcT4[64 * 512];

#define CHUNK_ELEMS (128 * 32)           // 4096 bf16 = 8192 B per image chunk
#define ROWB 80                          // smem row stride (32 bf16 + 16B pad)
#define MT_STRIDE (16 * ROWB)            // 1280

// Per-buffer SMEM: A_h@0(5120) A_l@5120(5120) W_h@10240(2x10240) W_l@30720(2x10240)
#define BUF_B   51200
#define OFF_AL  5120
#define OFF_WH  10240
#define OFF_WL  30720
#define SMEM_BYTES (2 * BUF_B)           // 102400

// ---------------------------------------------------------------------------
// Helpers (plain sm_103-safe PTX only)
// ---------------------------------------------------------------------------
__device__ __forceinline__ uint32_t smem_u32(const void* p) {
    uint32_t a;
    asm("{ .reg .u64 t; cvta.to.shared.u64 t, %1; cvt.u32.u64 %0, t; }"
        : "=r"(a) : "l"(p));
    return a;
}
__device__ __forceinline__ void ldmx4(uint32_t addr, uint32_t r[4]) {
    asm volatile("ldmatrix.sync.aligned.m8n8.x4.shared.b16 {%0,%1,%2,%3}, [%4];"
                 : "=r"(r[0]), "=r"(r[1]), "=r"(r[2]), "=r"(r[3]) : "r"(addr));
}
__device__ __forceinline__ void mma_bf16(float d[4], const uint32_t a[4],
                                         uint32_t b0, uint32_t b1) {
    asm volatile(
        "mma.sync.aligned.m16n8k16.row.col.f32.bf16.bf16.f32 "
        "{%0,%1,%2,%3},{%4,%5,%6,%7},{%8,%9},{%0,%1,%2,%3};"
        : "+f"(d[0]), "+f"(d[1]), "+f"(d[2]), "+f"(d[3])
        : "r"(a[0]), "r"(a[1]), "r"(a[2]), "r"(a[3]), "r"(b0), "r"(b1));
}
__device__ __forceinline__ void cp16(uint32_t dst, const void* src) {
    asm volatile("cp.async.cg.shared.global [%0], [%1], 16;" :: "r"(dst), "l"(src));
}
#define CP_COMMIT() asm volatile("cp.async.commit_group;" ::: "memory")
#define CP_WAIT0()  asm volatile("cp.async.wait_group 0;" ::: "memory")

__device__ __forceinline__ void split_store(char* Ah, char* Al, int r, int q,
                                            float x0, float x1, float x2, float x3) {
    __nv_bfloat16 h0 = __float2bfloat16(x0), h1 = __float2bfloat16(x1);
    __nv_bfloat16 h2 = __float2bfloat16(x2), h3 = __float2bfloat16(x3);
    __nv_bfloat16 l0 = __float2bfloat16(x0 - __bfloat162float(h0));
    __nv_bfloat16 l1 = __float2bfloat16(x1 - __bfloat162float(h1));
    __nv_bfloat16 l2 = __float2bfloat16(x2 - __bfloat162float(h2));
    __nv_bfloat16 l3 = __float2bfloat16(x3 - __bfloat162float(h3));
    __nv_bfloat162 p;
    char* dh = Ah + r * ROWB + q * 8;
    char* dl = Al + r * ROWB + q * 8;
    p.x = h0; p.y = h1; *(__nv_bfloat162*)dh = p;
    p.x = h2; p.y = h3; *(__nv_bfloat162*)(dh + 4) = p;
    p.x = l0; p.y = l1; *(__nv_bfloat162*)dl = p;
    p.x = l2; p.y = l3; *(__nv_bfloat162*)(dl + 4) = p;
}

// ---------------------------------------------------------------------------
// k0: split Wv1/Wv2 into bf16 hi/lo K=32-chunk images
// ---------------------------------------------------------------------------
__global__ void __launch_bounds__(256)
k0_wconv(const float* __restrict__ Wv1, const float* __restrict__ Wv2)
{
    int idx = blockIdx.x * 256 + threadIdx.x;
    if (idx < 512 * 512) {
        int c = idx >> 9, k = idx & 511;
        float v = Wv1[idx];
        __nv_bfloat16 h = __float2bfloat16(v);
        __nv_bfloat16 l = __float2bfloat16(v - __bfloat162float(h));
        int nc = c >> 7, nl = c & 127, kc = k >> 5, kk = k & 31;
        size_t d = ((size_t)(nc * 16 + kc) * 128 + nl) * 32 + kk;
        g_W1h[d] = h; g_W1l[d] = l;
    } else if (idx < 512 * 512 + 256 * 512) {
        int e = idx - 512 * 512;
        int j = e >> 9, k = e & 511;
        float v = Wv2[e];
        __nv_bfloat16 h = __float2bfloat16(v);
        __nv_bfloat16 l = __float2bfloat16(v - __bfloat162float(h));
        int nc = j >> 7, nl = j & 127, kc = k >> 5, kk = k & 31;
        size_t d = ((size_t)(nc * 16 + kc) * 128 + nl) * 32 + kk;
        g_W2h[d] = h; g_W2l[d] = l;
    }
}

// ---------------------------------------------------------------------------
// kt: transposed packed fp32 weights for k3
// ---------------------------------------------------------------------------
__global__ void __launch_bounds__(256)
kt_trans(const float* __restrict__ Wb, const float* __restrict__ Wc)
{
    int idx = blockIdx.x * 256 + threadIdx.x;
    if (idx < 128 * 256) {
        int k4 = idx >> 8, j = idx & 255;
        const float* s = Wb + (size_t)j * VD_ + k4 * 4;
        g_WbT4[idx] = make_float4(s[0], s[1], s[2], s[3]);
    } else if (idx < 128 * 256 + 64 * 512) {
        int e = idx - 128 * 256;
        int k4 = e >> 9, c = e & 511;
        const float* s = Wc + (size_t)c * HD_ + k4 * 4;
        g_WcT4[e] = make_float4(s[0], s[1], s[2], s[3]);
    }
}

// ---------------------------------------------------------------------------
// k1: audio features (proven, unchanged)
// ---------------------------------------------------------------------------
__global__ void __launch_bounds__(256)
k1_audio(const float* __restrict__ audio,
         const float* __restrict__ Wa1, const float* __restrict__ ba1,
         const float* __restrict__ Wa2, const float* __restrict__ ba2)
{
    __shared__ __align__(16) float af[32][AD_];
    const int tid = threadIdx.x;
    const int bt0 = blockIdx.x * 32;

    for (int idx = tid; idx < 32 * AD_; idx += 256) {
        int i = idx >> 7, k = idx & 127;
        int bt = bt0 + i;
        int b = bt / T_, t = bt - b * T_;
        af[i][k] = audio[((size_t)t * B_ + b) * AD_ + k];
    }
    __syncthreads();

    for (int c = tid; c < VD_; c += 256) {
        const float4* w4 = (const float4*)(Wa1 + (size_t)c * AD_);
        float acc[32];
#pragma unroll
        for (int i = 0; i < 32; ++i) acc[i] = 0.f;
        for (int k4 = 0; k4 < AD_ / 4; ++k4) {
            float4 w = w4[k4];
#pragma unroll
            for (int i = 0; i < 32; ++i) {
                float4 v = *(const float4*)&af[i][k4 * 4];
                acc[i] += v.x * w.x + v.y * w.y + v.z * w.z + v.w * w.w;
            }
        }
        float bias = ba1[c];
#pragma unroll
        for (int i = 0; i < 32; ++i)
            g_aq1[(size_t)(bt0 + i) * VD_ + c] = fmaxf(acc[i] + bias, 0.f);
    }
    {
        int j = tid;
        const float4* w4 = (const float4*)(Wa2 + (size_t)j * AD_);
        float acc[32];
#pragma unroll
        for (int i = 0; i < 32; ++i) acc[i] = 0.f;
        for (int k4 = 0; k4 < AD_ / 4; ++k4) {
            float4 w = w4[k4];
#pragma unroll
            for (int i = 0; i < 32; ++i) {
                float4 v = *(const float4*)&af[i][k4 * 4];
                acc[i] += v.x * w.x + v.y * w.y + v.z * w.z + v.w * w.w;
            }
        }
        float bias = ba2[j];
#pragma unroll
        for (int i = 0; i < 32; ++i)
            g_aq2[(size_t)(bt0 + i) * HD_ + j] = fmaxf(acc[i] + bias, 0.f);
    }
}

// ---------------------------------------------------------------------------
// W-chunk issue: 4 images x 8192B, re-strided 64B rows -> 80B smem rows
// ---------------------------------------------------------------------------
__device__ __forceinline__ void issue_w(
    uint32_t dstBase,
    const __nv_bfloat16* wH0, const __nv_bfloat16* wL0,
    const __nv_bfloat16* wH1, const __nv_bfloat16* wL1,
    int kc, int tid)
{
    const char* sH0 = (const char*)(wH0 + (size_t)kc * CHUNK_ELEMS);
    const char* sH1 = (const char*)(wH1 + (size_t)kc * CHUNK_ELEMS);
    const char* sL0 = (const char*)(wL0 + (size_t)kc * CHUNK_ELEMS);
    const char* sL1 = (const char*)(wL1 + (size_t)kc * CHUNK_ELEMS);
#pragma unroll
    for (int i = tid; i < 512; i += 256) {
        int r = i >> 2, q = i & 3;
        uint32_t dof = (uint32_t)(r * ROWB + q * 16);
        int sof = r * 64 + q * 16;
        cp16(dstBase + OFF_WH + dof,         sH0 + sof);
        cp16(dstBase + OFF_WH + 10240 + dof, sH1 + sof);
        cp16(dstBase + OFF_WL + dof,         sL0 + sof);
        cp16(dstBase + OFF_WL + 10240 + dof, sL1 + sof);
    }
}

// ---------------------------------------------------------------------------
// GEMM mainloop: M=64, N=256, K chunks of 32, DOUBLE-buffered, 2 CTAs/SM.
// Per chunk: wait W(kc); sync; issue W(kc+1); LDG video regs (A kc+1);
// MMA(kc); convert regs -> other buffer. One barrier per chunk.
// s_scale: per-clip 512-float SMEM array (g2) or nullptr (g1).
// ---------------------------------------------------------------------------
__device__ __forceinline__ void gemm_mainloop(
    float acc[2][8][4], char* sm, uint32_t aBase,
    const float* __restrict__ video, const float* s_scale,
    const __nv_bfloat16* wH0, const __nv_bfloat16* wL0,
    const __nv_bfloat16* wH1, const __nv_bfloat16* wL1,
    int bt, int tid, int lane, int wm, int wn)
{
    // zero pad rows 49..63 (64B data region) in both buffers, hi+lo
    if (tid < 240) {
        int r = 49 + tid / 16, w = (tid & 15) * 4;
#pragma unroll
        for (int b = 0; b < 2; ++b) {
            *(uint32_t*)(sm + b * BUF_B + r * ROWB + w) = 0u;
            *(uint32_t*)(sm + b * BUF_B + OFF_AL + r * ROWB + w) = 0u;
        }
    }

    // A conversion work split: 392 float4 items over 256 threads
    const int i0 = tid, i1 = tid + 256;
    const int r0 = i0 >> 3, q0 = i0 & 7;
    const int r1 = i1 >> 3, q1 = i1 & 7;
    const bool has1 = (i1 < 392);
    const float* vrow0 = video + ((size_t)bt * HW_ + r0) * VD_ + q0 * 4;
    const float* vrow1 = video + ((size_t)bt * HW_ + r1) * VD_ + q1 * 4;

    // per-lane ldmatrix offsets (within a buffer)
    const uint32_t oAh = (uint32_t)((wm * 32 + (lane & 15)) * ROWB
                        + ((lane >> 4) & 1) * 16);
    const uint32_t oBh = OFF_WH
                        + (uint32_t)((wn * 64 + (lane & 7) + ((lane >> 4) & 1) * 8) * ROWB
                        + ((lane >> 3) & 1) * 16);

    // prologue: convert chunk 0 -> buf0, issue W(0) -> buf0
    {
        float4 v0 = *(const float4*)vrow0;
        float4 v1 = has1 ? *(const float4*)vrow1 : make_float4(0.f, 0.f, 0.f, 0.f);
        if (s_scale) {
            float4 s0 = *(const float4*)(s_scale + q0 * 4);
            v0.x *= s0.x; v0.y *= s0.y; v0.z *= s0.z; v0.w *= s0.w;
            if (has1) {
                float4 s1 = *(const float4*)(s_scale + q1 * 4);
                v1.x *= s1.x; v1.y *= s1.y; v1.z *= s1.z; v1.w *= s1.w;
            }
        }
        split_store(sm, sm + OFF_AL, r0, q0, v0.x, v0.y, v0.z, v0.w);
        if (has1) split_store(sm, sm + OFF_AL, r1, q1, v1.x, v1.y, v1.z, v1.w);
        issue_w(aBase, wH0, wL0, wH1, wL1, 0, tid);
        CP_COMMIT();
    }

    for (int kc = 0; kc < 16; ++kc) {
        const int p = kc & 1;
        const uint32_t bp = aBase + p * BUF_B;
        char* bq = sm + (p ^ 1) * BUF_B;
        CP_WAIT0();
        __syncthreads();   // W(kc)+A(kc) visible; all prior reads of buf p^1 done

        float4 v0, v1;
        if (kc < 15) {
            issue_w(aBase + (p ^ 1) * BUF_B, wH0, wL0, wH1, wL1, kc + 1, tid);
            CP_COMMIT();
            v0 = *(const float4*)(vrow0 + (kc + 1) * 32);     // LDG hidden by MMA
            if (has1) v1 = *(const float4*)(vrow1 + (kc + 1) * 32);
        }

        // MMA on chunk kc (buffer p)
#pragma unroll
        for (int ks = 0; ks < 2; ++ks) {
            uint32_t ah[2][4], al[2][4];
#pragma unroll
            for (int mt = 0; mt < 2; ++mt) {
                ldmx4(bp + oAh + mt * MT_STRIDE + ks * 32, ah[mt]);
                ldmx4(bp + OFF_AL + oAh + mt * MT_STRIDE + ks * 32, al[mt]);
            }
#pragma unroll
            for (int np = 0; np < 4; ++np) {
                uint32_t bh4[4], bl4[4];
                ldmx4(bp + oBh + np * MT_STRIDE + ks * 32, bh4);
                ldmx4(bp + oBh + (OFF_WL - OFF_WH) + np * MT_STRIDE + ks * 32, bl4);
#pragma unroll
                for (int mt = 0; mt < 2; ++mt)
#pragma unroll
                    for (int sub = 0; sub < 2; ++sub) {
                        int nt = np * 2 + sub, s = sub * 2;
                        mma_bf16(acc[mt][nt], ah[mt], bh4[s], bh4[s + 1]);
                        mma_bf16(acc[mt][nt], al[mt], bh4[s], bh4[s + 1]);
                        mma_bf16(acc[mt][nt], ah[mt], bl4[s], bl4[s + 1]);
                    }
            }
        }

        // convert prefetched regs -> buffer p^1 (scale read from SMEM, cheap)
        if (kc < 15) {
            if (s_scale) {
                float4 s0 = *(const float4*)(s_scale + (kc + 1) * 32 + q0 * 4);
                v0.x *= s0.x; v0.y *= s0.y; v0.z *= s0.z; v0.w *= s0.w;
                if (has1) {
                    float4 s1 = *(const float4*)(s_scale + (kc + 1) * 32 + q1 * 4);
                    v1.x *= s1.x; v1.y *= s1.y; v1.z *= s1.z; v1.w *= s1.w;
                }
            }
            split_store(bq, bq + OFF_AL, r0, q0, v0.x, v0.y, v0.z, v0.w);
            if (has1) split_store(bq, bq + OFF_AL, r1, q1, v1.x, v1.y, v1.z, v1.w);
        }
    }
    __syncthreads();   // smem free for epilogue reuse
}

// ---------------------------------------------------------------------------
// g1: GEMM1 + relu + hw-mean + x aq1/49 -> g_m1.  grid = (2 n-halves, 2560)
// ---------------------------------------------------------------------------
__global__ void __launch_bounds__(256, 2)
g1_mma(const float* __restrict__ video, const float* __restrict__ bv1)
{
    extern __shared__ char sm[];
    const int tid = threadIdx.x, wid = tid >> 5, lane = tid & 31;
    const int wm = wid >> 2, wn = wid & 3;
    const int nh = blockIdx.x, bt = blockIdx.y;
    const uint32_t aBase = smem_u32(sm);

    float acc[2][8][4];
#pragma unroll
    for (int a = 0; a < 2; ++a)
#pragma unroll
        for (int b = 0; b < 8; ++b)
#pragma unroll
            for (int c = 0; c < 4; ++c) acc[a][b][c] = 0.f;

    gemm_mainloop(acc, sm, aBase, video, nullptr,
                  g_W1h + (size_t)(nh * 2)     * 16 * CHUNK_ELEMS,
                  g_W1l + (size_t)(nh * 2)     * 16 * CHUNK_ELEMS,
                  g_W1h + (size_t)(nh * 2 + 1) * 16 * CHUNK_ELEMS,
                  g_W1l + (size_t)(nh * 2 + 1) * 16 * CHUNK_ELEMS,
                  bt, tid, lane, wm, wn);

    // stage relu(D + bias) into smem [64][260]
    float* stage = (float*)sm;
#pragma unroll
    for (int mt = 0; mt < 2; ++mt)
#pragma unroll
        for (int nt = 0; nt < 8; ++nt) {
            int r0 = wm * 32 + mt * 16 + (lane >> 2);
            int c0 = wn * 64 + nt * 8 + (lane & 3) * 2;
            float b0 = bv1[nh * 256 + c0], b1 = bv1[nh * 256 + c0 + 1];
            stage[r0 * 260 + c0]           = fmaxf(acc[mt][nt][0] + b0, 0.f);
            stage[r0 * 260 + c0 + 1]       = fmaxf(acc[mt][nt][1] + b1, 0.f);
            stage[(r0 + 8) * 260 + c0]     = fmaxf(acc[mt][nt][2] + b0, 0.f);
            stage[(r0 + 8) * 260 + c0 + 1] = fmaxf(acc[mt][nt][3] + b1, 0.f);
        }
    __syncthreads();

    {
        float s = 0.f;
#pragma unroll
        for (int h = 0; h < HW_; ++h) s += stage[h * 260 + tid];
        int c = nh * 256 + tid;
        g_m1[(size_t)bt * VD_ + c] =
            g_aq1[(size_t)bt * VD_ + c] * s * (1.f / 49.f);
    }
}

// ---------------------------------------------------------------------------
// k3: channel-attention MLP, coalesced transposed weights, 16 clips/block
// ---------------------------------------------------------------------------
__global__ void __launch_bounds__(256)
k3_catt(const float* __restrict__ bb, const float* __restrict__ bc)
{
    __shared__ __align__(16) float4 m1s4[16 * 128];
    __shared__ __align__(16) float t1s[16][HD_];
    const int tid = threadIdx.x;
    const int bt0 = blockIdx.x * 16;

    {
        const float4* src = (const float4*)(g_m1 + (size_t)bt0 * VD_);
        for (int i = tid; i < 16 * 128; i += 256) m1s4[i] = src[i];
    }
    __syncthreads();
    {
        const int j = tid;
        float acc[16];
#pragma unroll
        for (int i = 0; i < 16; ++i) acc[i] = 0.f;
        for (int k4 = 0; k4 < 128; ++k4) {
            float4 w = g_WbT4[k4 * 256 + j];
#pragma unroll
            for (int i = 0; i < 16; ++i) {
                float4 v = m1s4[i * 128 + k4];
                acc[i] += v.x * w.x + v.y * w.y + v.z * w.z + v.w * w.w;
            }
        }
        float bias = bb[j];
#pragma unroll
        for (int i = 0; i < 16; ++i) t1s[i][j] = fmaxf(acc[i] + bias, 0.f);
    }
    __syncthreads();
    {
        const int c0 = tid, c1 = tid + 256;
        float acc0[16], acc1[16];
#pragma unroll
        for (int i = 0; i < 16; ++i) { acc0[i] = 0.f; acc1[i] = 0.f; }
        for (int k4 = 0; k4 < 64; ++k4) {
            float4 w0 = g_WcT4[k4 * 512 + c0];
            float4 w1 = g_WcT4[k4 * 512 + c1];
#pragma unroll
            for (int i = 0; i < 16; ++i) {
                float4 v = *(const float4*)&t1s[i][k4 * 4];
                acc0[i] += v.x * w0.x + v.y * w0.y + v.z * w0.z + v.w * w0.w;
                acc1[i] += v.x * w1.x + v.y * w1.y + v.z * w1.z + v.w * w1.w;
            }
        }
        float b0 = bc[c0], b1 = bc[c1];
#pragma unroll
        for (int i = 0; i < 16; ++i) {
            float x0 = acc0[i] + b0, x1 = acc1[i] + b1;
            g_scale[(size_t)(bt0 + i) * VD_ + c0] = 1.f + 1.f / (1.f + expf(-x0));
            g_scale[(size_t)(bt0 + i) * VD_ + c1] = 1.f + 1.f / (1.f + expf(-x1));
        }
    }
}

// ---------------------------------------------------------------------------
// g2: GEMM2 + relu x (aq2*Ws) row sums + tanh/softmax + output, grid = 2560
// ---------------------------------------------------------------------------
__global__ void __launch_bounds__(256, 2)
g2_mma(const float* __restrict__ video, const float* __restrict__ bv2,
       const float* __restrict__ Ws, const float* __restrict__ bs,
       float* __restrict__ out)
{
    extern __shared__ char sm[];
    __shared__ float u_s[256];
    __shared__ __align__(16) float s_scale[512];
    __shared__ float part[64];
    __shared__ float swt[64];
    __shared__ float smx, sdn;
    const int tid = threadIdx.x, wid = tid >> 5, lane = tid & 31;
    const int wm = wid >> 2, wn = wid & 3;
    const int bt = blockIdx.x;
    const uint32_t aBase = smem_u32(sm);

    u_s[tid] = g_aq2[(size_t)bt * HD_ + tid] * Ws[tid];
    s_scale[tid]       = g_scale[(size_t)bt * VD_ + tid];
    s_scale[tid + 256] = g_scale[(size_t)bt * VD_ + tid + 256];
    if (tid < 64) part[tid] = 0.f;
    __syncthreads();   // s_scale ready before mainloop prologue reads it

    float acc[2][8][4];
#pragma unroll
    for (int a = 0; a < 2; ++a)
#pragma unroll
        for (int b = 0; b < 8; ++b)
#pragma unroll
            for (int c = 0; c < 4; ++c) acc[a][b][c] = 0.f;

    gemm_mainloop(acc, sm, aBase, video, s_scale,
                  g_W2h, g_W2l,
                  g_W2h + (size_t)16 * CHUNK_ELEMS,
                  g_W2l + (size_t)16 * CHUNK_ELEMS,
                  bt, tid, lane, wm, wn);

    // row sums: sum_j relu(D + bv2[j]) * u[j]
#pragma unroll
    for (int mt = 0; mt < 2; ++mt) {
        int r0 = wm * 32 + mt * 16 + (lane >> 2);
        float s0 = 0.f, s1 = 0.f;
#pragma unroll
        for (int nt = 0; nt < 8; ++nt) {
            int c0 = wn * 64 + nt * 8 + (lane & 3) * 2;
            float b0 = bv2[c0], b1 = bv2[c0 + 1];
            float u0 = u_s[c0], u1 = u_s[c0 + 1];
            s0 += fmaxf(acc[mt][nt][0] + b0, 0.f) * u0
                + fmaxf(acc[mt][nt][1] + b1, 0.f) * u1;
            s1 += fmaxf(acc[mt][nt][2] + b0, 0.f) * u0
                + fmaxf(acc[mt][nt][3] + b1, 0.f) * u1;
        }
        s0 += __shfl_xor_sync(0xffffffffu, s0, 1);
        s0 += __shfl_xor_sync(0xffffffffu, s0, 2);
        s1 += __shfl_xor_sync(0xffffffffu, s1, 1);
        s1 += __shfl_xor_sync(0xffffffffu, s1, 2);
        if ((lane & 3) == 0) {
            atomicAdd(&part[r0], s0);
            atomicAdd(&part[r0 + 8], s1);
        }
    }
    __syncthreads();

    if (tid < HW_) swt[tid] = tanhf(part[tid] + bs[0]);
    __syncthreads();
    if (tid == 0) {
        float mx = -1e30f;
        for (int h = 0; h < HW_; ++h) mx = fmaxf(mx, swt[h]);
        float den = 0.f;
        for (int h = 0; h < HW_; ++h) den += expf(swt[h] - mx);
        smx = mx; sdn = den;
    }
    __syncthreads();
    if (tid < HW_) swt[tid] = expf(swt[tid] - smx) / sdn;
    __syncthreads();

    for (int c = tid; c < VD_; c += 256) {
        float a = 0.f;
#pragma unroll 7
        for (int h = 0; h < HW_; ++h)
            a += swt[h] * video[((size_t)bt * HW_ + h) * VD_ + c];
        out[(size_t)bt * VD_ + c] = a * s_scale[c];
    }
}

// ---------------------------------------------------------------------------
// Launch
// ---------------------------------------------------------------------------
extern "C" void kernel_launch(void* const* d_in, const int* in_sizes, int n_in,
                              void* d_out, int out_size)
{
    const float* video = (const float*)d_in[0];
    const float* audio = (const float*)d_in[1];
    const float* Wv1   = (const float*)d_in[2];
    const float* bv1   = (const float*)d_in[3];
    const float* Wa1   = (const float*)d_in[4];
    const float* ba1   = (const float*)d_in[5];
    const float* Wb    = (const float*)d_in[6];
    const float* bb    = (const float*)d_in[7];
    const float* Wc    = (const float*)d_in[8];
    const float* bc    = (const float*)d_in[9];
    const float* Wv2   = (const float*)d_in[10];
    const float* bv2   = (const float*)d_in[11];
    const float* Wa2   = (const float*)d_in[12];
    const float* ba2   = (const float*)d_in[13];
    const float* Ws    = (const float*)d_in[14];
    const float* bs    = (const float*)d_in[15];
    float* out = (float*)d_out;

    cudaFuncSetAttribute(g1_mma, cudaFuncAttributeMaxDynamicSharedMemorySize, SMEM_BYTES);
    cudaFuncSetAttribute(g2_mma, cudaFuncAttributeMaxDynamicSharedMemorySize, SMEM_BYTES);

    k0_wconv<<<1536, 256>>>(Wv1, Wv2);
    kt_trans<<<256, 256>>>(Wb, Wc);
    k1_audio<<<BT_ / 32, 256>>>(audio, Wa1, ba1, Wa2, ba2);
    g1_mma<<<dim3(2, BT_), 256, SMEM_BYTES>>>(video, bv1);
    k3_catt<<<BT_ / 16, 256>>>(bb, bc);
    g2_mma<<<BT_, 256, SMEM_BYTES>>>(video, bv2, Ws, bs, out);
}

// round 13
// speedup vs baseline: 1.1323x; 1.0105x over previous
#include <cuda_runtime.h>
#include <cuda_bf16.h>
#include <cstdint>

#define B_   256
#define T_   10
#define BT_  2560
#define HW_  49
#define VD_  512
#define AD_  128
#define HD_  256

// ---------------------------------------------------------------------------
// Scratch (__device__ globals — allocation-free)
// ---------------------------------------------------------------------------
__device__ float g_aq1[BT_ * VD_];
__device__ float g_aq2[BT_ * HD_];
__device__ float g_m1 [BT_ * VD_];
__device__ float g_scale[BT_ * VD_];

// Pre-split bf16 weight images, K=32 chunks, unpadded 64B rows:
// [n_chunk][k_chunk(16)][128 n-rows][32 k]
__device__ __align__(16) __nv_bfloat16 g_W1h[4 * 16 * 128 * 32];
__device__ __align__(16) __nv_bfloat16 g_W1l[4 * 16 * 128 * 32];
__device__ __align__(16) __nv_bfloat16 g_W2h[2 * 16 * 128 * 32];
__device__ __align__(16) __nv_bfloat16 g_W2l[2 * 16 * 128 * 32];

// Transposed packed fp32 weights for k3
__device__ __align__(16) float4 g_WbT4[128 * 256];
__device__ __align__(16) float4 g_WcT4[64 * 512];

#define CHUNK_ELEMS (128 * 32)           // 4096 bf16 = 8192 B per image chunk
#define ROWB 80                          // smem row stride (32 bf16 + 16B pad)
#define MT_STRIDE (16 * ROWB)            // 1280
#define OFF_AL  5120
#define OFF_WH  10240

// ---------------------------------------------------------------------------
// Helpers (plain sm_103-safe PTX only)
// ---------------------------------------------------------------------------
__device__ __forceinline__ uint32_t smem_u32(const void* p) {
    uint32_t a;
    asm("{ .reg .u64 t; cvta.to.shared.u64 t, %1; cvt.u32.u64 %0, t; }"
        : "=r"(a) : "l"(p));
    return a;
}
__device__ __forceinline__ void ldmx4(uint32_t addr, uint32_t r[4]) {
    asm volatile("ldmatrix.sync.aligned.m8n8.x4.shared.b16 {%0,%1,%2,%3}, [%4];"
                 : "=r"(r[0]), "=r"(r[1]), "=r"(r[2]), "=r"(r[3]) : "r"(addr));
}
__device__ __forceinline__ void mma_bf16(float d[4], const uint32_t a[4],
                                         uint32_t b0, uint32_t b1) {
    asm volatile(
        "mma.sync.aligned.m16n8k16.row.col.f32.bf16.bf16.f32 "
        "{%0,%1,%2,%3},{%4,%5,%6,%7},{%8,%9},{%0,%1,%2,%3};"
        : "+f"(d[0]), "+f"(d[1]), "+f"(d[2]), "+f"(d[3])
        : "r"(a[0]), "r"(a[1]), "r"(a[2]), "r"(a[3]), "r"(b0), "r"(b1));
}
__device__ __forceinline__ void cp16(uint32_t dst, const void* src) {
    asm volatile("cp.async.cg.shared.global [%0], [%1], 16;" :: "r"(dst), "l"(src));
}
#define CP_COMMIT() asm volatile("cp.async.commit_group;" ::: "memory")
#define CP_WAIT0()  asm volatile("cp.async.wait_group 0;" ::: "memory")

__device__ __forceinline__ void split_store(char* Ah, char* Al, int r, int q,
                                            float x0, float x1, float x2, float x3) {
    __nv_bfloat16 h0 = __float2bfloat16(x0), h1 = __float2bfloat16(x1);
    __nv_bfloat16 h2 = __float2bfloat16(x2), h3 = __float2bfloat16(x3);
    __nv_bfloat16 l0 = __float2bfloat16(x0 - __bfloat162float(h0));
    __nv_bfloat16 l1 = __float2bfloat16(x1 - __bfloat162float(h1));
    __nv_bfloat16 l2 = __float2bfloat16(x2 - __bfloat162float(h2));
    __nv_bfloat16 l3 = __float2bfloat16(x3 - __bfloat162float(h3));
    __nv_bfloat162 p;
    char* dh = Ah + r * ROWB + q * 8;
    char* dl = Al + r * ROWB + q * 8;
    p.x = h0; p.y = h1; *(__nv_bfloat162*)dh = p;
    p.x = h2; p.y = h3; *(__nv_bfloat162*)(dh + 4) = p;
    p.x = l0; p.y = l1; *(__nv_bfloat162*)dl = p;
    p.x = l2; p.y = l3; *(__nv_bfloat162*)(dl + 4) = p;
}

// ---------------------------------------------------------------------------
// k0 / kt / k1: unchanged proven pre-pass kernels
// ---------------------------------------------------------------------------
__global__ void __launch_bounds__(256)
k0_wconv(const float* __restrict__ Wv1, const float* __restrict__ Wv2)
{
    int idx = blockIdx.x * 256 + threadIdx.x;
    if (idx < 512 * 512) {
        int c = idx >> 9, k = idx & 511;
        float v = Wv1[idx];
        __nv_bfloat16 h = __float2bfloat16(v);
        __nv_bfloat16 l = __float2bfloat16(v - __bfloat162float(h));
        int nc = c >> 7, nl = c & 127, kc = k >> 5, kk = k & 31;
        size_t d = ((size_t)(nc * 16 + kc) * 128 + nl) * 32 + kk;
        g_W1h[d] = h; g_W1l[d] = l;
    } else if (idx < 512 * 512 + 256 * 512) {
        int e = idx - 512 * 512;
        int j = e >> 9, k = e & 511;
        float v = Wv2[e];
        __nv_bfloat16 h = __float2bfloat16(v);
        __nv_bfloat16 l = __float2bfloat16(v - __bfloat162float(h));
        int nc = j >> 7, nl = j & 127, kc = k >> 5, kk = k & 31;
        size_t d = ((size_t)(nc * 16 + kc) * 128 + nl) * 32 + kk;
        g_W2h[d] = h; g_W2l[d] = l;
    }
}

__global__ void __launch_bounds__(256)
kt_trans(const float* __restrict__ Wb, const float* __restrict__ Wc)
{
    int idx = blockIdx.x * 256 + threadIdx.x;
    if (idx < 128 * 256) {
        int k4 = idx >> 8, j = idx & 255;
        const float* s = Wb + (size_t)j * VD_ + k4 * 4;
        g_WbT4[idx] = make_float4(s[0], s[1], s[2], s[3]);
    } else if (idx < 128 * 256 + 64 * 512) {
        int e = idx - 128 * 256;
        int k4 = e >> 9, c = e & 511;
        const float* s = Wc + (size_t)c * HD_ + k4 * 4;
        g_WcT4[e] = make_float4(s[0], s[1], s[2], s[3]);
    }
}

__global__ void __launch_bounds__(256)
k1_audio(const float* __restrict__ audio,
         const float* __restrict__ Wa1, const float* __restrict__ ba1,
         const float* __restrict__ Wa2, const float* __restrict__ ba2)
{
    __shared__ __align__(16) float af[32][AD_];
    const int tid = threadIdx.x;
    const int bt0 = blockIdx.x * 32;

    for (int idx = tid; idx < 32 * AD_; idx += 256) {
        int i = idx >> 7, k = idx & 127;
        int bt = bt0 + i;
        int b = bt / T_, t = bt - b * T_;
        af[i][k] = audio[((size_t)t * B_ + b) * AD_ + k];
    }
    __syncthreads();

    for (int c = tid; c < VD_; c += 256) {
        const float4* w4 = (const float4*)(Wa1 + (size_t)c * AD_);
        float acc[32];
#pragma unroll
        for (int i = 0; i < 32; ++i) acc[i] = 0.f;
        for (int k4 = 0; k4 < AD_ / 4; ++k4) {
            float4 w = w4[k4];
#pragma unroll
            for (int i = 0; i < 32; ++i) {
                float4 v = *(const float4*)&af[i][k4 * 4];
                acc[i] += v.x * w.x + v.y * w.y + v.z * w.z + v.w * w.w;
            }
        }
        float bias = ba1[c];
#pragma unroll
        for (int i = 0; i < 32; ++i)
            g_aq1[(size_t)(bt0 + i) * VD_ + c] = fmaxf(acc[i] + bias, 0.f);
    }
    {
        int j = tid;
        const float4* w4 = (const float4*)(Wa2 + (size_t)j * AD_);
        float acc[32];
#pragma unroll
        for (int i = 0; i < 32; ++i) acc[i] = 0.f;
        for (int k4 = 0; k4 < AD_ / 4; ++k4) {
            float4 w = w4[k4];
#pragma unroll
            for (int i = 0; i < 32; ++i) {
                float4 v = *(const float4*)&af[i][k4 * 4];
                acc[i] += v.x * w.x + v.y * w.y + v.z * w.z + v.w * w.w;
            }
        }
        float bias = ba2[j];
#pragma unroll
        for (int i = 0; i < 32; ++i)
            g_aq2[(size_t)(bt0 + i) * HD_ + j] = fmaxf(acc[i] + bias, 0.f);
    }
}

// ---------------------------------------------------------------------------
// Templated GEMM mainloop (NP = number of 64-row W image halves per... i.e.
// N = NP*64). NP=2: g1 (N=128, 3 CTAs/SM). NP=4: g2 (N=256, 2 CTAs/SM).
// Double-buffered K=32 chunks, one barrier per chunk (R12-proven schedule).
// ---------------------------------------------------------------------------
template<int NP>
__device__ __forceinline__ void gemm_mainloop_t(
    float acc[2][NP * 2][4], char* sm, uint32_t aBase,
    const float* __restrict__ video, const float* s_scale,
    const __nv_bfloat16* wH0, const __nv_bfloat16* wL0,
    const __nv_bfloat16* wH1, const __nv_bfloat16* wL1,
    int bt, int tid, int lane, int wm, int wn)
{
    constexpr int WSZ   = NP * 5120;          // W bytes per component
    constexpr int OFF_WL_ = OFF_WH + WSZ;
    constexpr int BUF_  = OFF_WH + 2 * WSZ;   // per-buffer bytes

    // zero pad rows 49..63 (64B data region) in both buffers, hi+lo
    if (tid < 240) {
        int r = 49 + tid / 16, w = (tid & 15) * 4;
#pragma unroll
        for (int b = 0; b < 2; ++b) {
            *(uint32_t*)(sm + b * BUF_ + r * ROWB + w) = 0u;
            *(uint32_t*)(sm + b * BUF_ + OFF_AL + r * ROWB + w) = 0u;
        }
    }

    // A conversion work split: 392 float4 items over 256 threads
    const int i0 = tid, i1 = tid + 256;
    const int r0 = i0 >> 3, q0 = i0 & 7;
    const int r1 = i1 >> 3, q1 = i1 & 7;
    const bool has1 = (i1 < 392);
    const float* vrow0 = video + ((size_t)bt * HW_ + r0) * VD_ + q0 * 4;
    const float* vrow1 = video + ((size_t)bt * HW_ + r1) * VD_ + q1 * 4;

    // per-lane ldmatrix offsets (within a buffer); warp N span = NP*16 rows
    const uint32_t oAh = (uint32_t)((wm * 32 + (lane & 15)) * ROWB
                        + ((lane >> 4) & 1) * 16);
    const uint32_t oBh = OFF_WH
                        + (uint32_t)((wn * (NP * 16) + (lane & 7) + ((lane >> 4) & 1) * 8) * ROWB
                        + ((lane >> 3) & 1) * 16);

    // W-chunk issue helper (inlined lambda)
    auto issue_w = [&](uint32_t dstBase, int kc) {
        const char* sH0 = (const char*)(wH0 + (size_t)kc * CHUNK_ELEMS);
        const char* sL0 = (const char*)(wL0 + (size_t)kc * CHUNK_ELEMS);
        const char* sH1 = (const char*)(wH1 + (size_t)kc * CHUNK_ELEMS);
        const char* sL1 = (const char*)(wL1 + (size_t)kc * CHUNK_ELEMS);
#pragma unroll
        for (int i = tid; i < 512; i += 256) {
            int r = i >> 2, q = i & 3;
            uint32_t dof = (uint32_t)(r * ROWB + q * 16);
            int sof = r * 64 + q * 16;
            cp16(dstBase + OFF_WH + dof, sH0 + sof);
            cp16(dstBase + OFF_WL_ + dof, sL0 + sof);
            if (NP == 4) {
                cp16(dstBase + OFF_WH + 10240 + dof, sH1 + sof);
                cp16(dstBase + OFF_WL_ + 10240 + dof, sL1 + sof);
            }
        }
    };

    // prologue: convert chunk 0 -> buf0, issue W(0) -> buf0
    {
        float4 v0 = *(const float4*)vrow0;
        float4 v1 = has1 ? *(const float4*)vrow1 : make_float4(0.f, 0.f, 0.f, 0.f);
        if (s_scale) {
            float4 s0 = *(const float4*)(s_scale + q0 * 4);
            v0.x *= s0.x; v0.y *= s0.y; v0.z *= s0.z; v0.w *= s0.w;
            if (has1) {
                float4 s1 = *(const float4*)(s_scale + q1 * 4);
                v1.x *= s1.x; v1.y *= s1.y; v1.z *= s1.z; v1.w *= s1.w;
            }
        }
        split_store(sm, sm + OFF_AL, r0, q0, v0.x, v0.y, v0.z, v0.w);
        if (has1) split_store(sm, sm + OFF_AL, r1, q1, v1.x, v1.y, v1.z, v1.w);
        issue_w(aBase, 0);
        CP_COMMIT();
    }

    for (int kc = 0; kc < 16; ++kc) {
        const int p = kc & 1;
        const uint32_t bp = aBase + p * BUF_;
        char* bq = sm + (p ^ 1) * BUF_;
        CP_WAIT0();
        __syncthreads();

        float4 v0, v1;
        if (kc < 15) {
            issue_w(aBase + (p ^ 1) * BUF_, kc + 1);
            CP_COMMIT();
            v0 = *(const float4*)(vrow0 + (kc + 1) * 32);
            if (has1) v1 = *(const float4*)(vrow1 + (kc + 1) * 32);
        }

        // MMA on chunk kc (buffer p)
#pragma unroll
        for (int ks = 0; ks < 2; ++ks) {
            uint32_t ah[2][4], al[2][4];
#pragma unroll
            for (int mt = 0; mt < 2; ++mt) {
                ldmx4(bp + oAh + mt * MT_STRIDE + ks * 32, ah[mt]);
                ldmx4(bp + OFF_AL + oAh + mt * MT_STRIDE + ks * 32, al[mt]);
            }
#pragma unroll
            for (int np = 0; np < NP; ++np) {
                uint32_t bh4[4], bl4[4];
                ldmx4(bp + oBh + np * MT_STRIDE + ks * 32, bh4);
                ldmx4(bp + oBh + WSZ + np * MT_STRIDE + ks * 32, bl4);
#pragma unroll
                for (int mt = 0; mt < 2; ++mt)
#pragma unroll
                    for (int sub = 0; sub < 2; ++sub) {
                        int nt = np * 2 + sub, s = sub * 2;
                        mma_bf16(acc[mt][nt], ah[mt], bh4[s], bh4[s + 1]);
                        mma_bf16(acc[mt][nt], al[mt], bh4[s], bh4[s + 1]);
                        mma_bf16(acc[mt][nt], ah[mt], bl4[s], bl4[s + 1]);
                    }
            }
        }

        // convert prefetched regs -> buffer p^1
        if (kc < 15) {
            if (s_scale) {
                float4 s0 = *(const float4*)(s_scale + (kc + 1) * 32 + q0 * 4);
                v0.x *= s0.x; v0.y *= s0.y; v0.z *= s0.z; v0.w *= s0.w;
                if (has1) {
                    float4 s1 = *(const float4*)(s_scale + (kc + 1) * 32 + q1 * 4);
                    v1.x *= s1.x; v1.y *= s1.y; v1.z *= s1.z; v1.w *= s1.w;
                }
            }
            split_store(bq, bq + OFF_AL, r0, q0, v0.x, v0.y, v0.z, v0.w);
            if (has1) split_store(bq, bq + OFF_AL, r1, q1, v1.x, v1.y, v1.z, v1.w);
        }
    }
    __syncthreads();   // smem free for epilogue reuse
}

// ---------------------------------------------------------------------------
// g1: GEMM1, N=128 tiles, 3 CTAs/SM.  grid = (4 n-chunks, 2560)
// ---------------------------------------------------------------------------
#define SMEM_G1 61440
__global__ void __launch_bounds__(256, 3)
g1_mma(const float* __restrict__ video, const float* __restrict__ bv1)
{
    extern __shared__ char sm[];
    const int tid = threadIdx.x, wid = tid >> 5, lane = tid & 31;
    const int wm = wid >> 2, wn = wid & 3;
    const int nc = blockIdx.x, bt = blockIdx.y;
    const uint32_t aBase = smem_u32(sm);

    float acc[2][4][4];
#pragma unroll
    for (int a = 0; a < 2; ++a)
#pragma unroll
        for (int b = 0; b < 4; ++b)
#pragma unroll
            for (int c = 0; c < 4; ++c) acc[a][b][c] = 0.f;

    gemm_mainloop_t<2>(acc, sm, aBase, video, nullptr,
                       g_W1h + (size_t)nc * 16 * CHUNK_ELEMS,
                       g_W1l + (size_t)nc * 16 * CHUNK_ELEMS,
                       nullptr, nullptr,
                       bt, tid, lane, wm, wn);

    // stage relu(D + bias) into smem [64][132]
    float* stage = (float*)sm;
#pragma unroll
    for (int mt = 0; mt < 2; ++mt)
#pragma unroll
        for (int nt = 0; nt < 4; ++nt) {
            int r0 = wm * 32 + mt * 16 + (lane >> 2);
            int c0 = wn * 32 + nt * 8 + (lane & 3) * 2;
            float b0 = bv1[nc * 128 + c0], b1 = bv1[nc * 128 + c0 + 1];
            stage[r0 * 132 + c0]           = fmaxf(acc[mt][nt][0] + b0, 0.f);
            stage[r0 * 132 + c0 + 1]       = fmaxf(acc[mt][nt][1] + b1, 0.f);
            stage[(r0 + 8) * 132 + c0]     = fmaxf(acc[mt][nt][2] + b0, 0.f);
            stage[(r0 + 8) * 132 + c0 + 1] = fmaxf(acc[mt][nt][3] + b1, 0.f);
        }
    __syncthreads();

    if (tid < 128) {
        float s = 0.f;
#pragma unroll
        for (int h = 0; h < HW_; ++h) s += stage[h * 132 + tid];
        int c = nc * 128 + tid;
        g_m1[(size_t)bt * VD_ + c] =
            g_aq1[(size_t)bt * VD_ + c] * s * (1.f / 49.f);
    }
}

// ---------------------------------------------------------------------------
// k3: channel-attention MLP (R11-proven coalesced variant)
// ---------------------------------------------------------------------------
__global__ void __launch_bounds__(256)
k3_catt(const float* __restrict__ bb, const float* __restrict__ bc)
{
    __shared__ __align__(16) float4 m1s4[16 * 128];
    __shared__ __align__(16) float t1s[16][HD_];
    const int tid = threadIdx.x;
    const int bt0 = blockIdx.x * 16;

    {
        const float4* src = (const float4*)(g_m1 + (size_t)bt0 * VD_);
        for (int i = tid; i < 16 * 128; i += 256) m1s4[i] = src[i];
    }
    __syncthreads();
    {
        const int j = tid;
        float acc[16];
#pragma unroll
        for (int i = 0; i < 16; ++i) acc[i] = 0.f;
        for (int k4 = 0; k4 < 128; ++k4) {
            float4 w = g_WbT4[k4 * 256 + j];
#pragma unroll
            for (int i = 0; i < 16; ++i) {
                float4 v = m1s4[i * 128 + k4];
                acc[i] += v.x * w.x + v.y * w.y + v.z * w.z + v.w * w.w;
            }
        }
        float bias = bb[j];
#pragma unroll
        for (int i = 0; i < 16; ++i) t1s[i][j] = fmaxf(acc[i] + bias, 0.f);
    }
    __syncthreads();
    {
        const int c0 = tid, c1 = tid + 256;
        float acc0[16], acc1[16];
#pragma unroll
        for (int i = 0; i < 16; ++i) { acc0[i] = 0.f; acc1[i] = 0.f; }
        for (int k4 = 0; k4 < 64; ++k4) {
            float4 w0 = g_WcT4[k4 * 512 + c0];
            float4 w1 = g_WcT4[k4 * 512 + c1];
#pragma unroll
            for (int i = 0; i < 16; ++i) {
                float4 v = *(const float4*)&t1s[i][k4 * 4];
                acc0[i] += v.x * w0.x + v.y * w0.y + v.z * w0.z + v.w * w0.w;
                acc1[i] += v.x * w1.x + v.y * w1.y + v.z * w1.z + v.w * w1.w;
            }
        }
        float b0 = bc[c0], b1 = bc[c1];
#pragma unroll
        for (int i = 0; i < 16; ++i) {
            float x0 = acc0[i] + b0, x1 = acc1[i] + b1;
            g_scale[(size_t)(bt0 + i) * VD_ + c0] = 1.f + 1.f / (1.f + expf(-x0));
            g_scale[(size_t)(bt0 + i) * VD_ + c1] = 1.f + 1.f / (1.f + expf(-x1));
        }
    }
}

// ---------------------------------------------------------------------------
// g2: GEMM2 (N=256) + relu x (aq2*Ws) + tanh/softmax + output, grid = 2560
// (byte-identical math to R12)
// ---------------------------------------------------------------------------
#define SMEM_G2 102400
__global__ void __launch_bounds__(256, 2)
g2_mma(const float* __restrict__ video, const float* __restrict__ bv2,
       const float* __restrict__ Ws, const float* __restrict__ bs,
       float* __restrict__ out)
{
    extern __shared__ char sm[];
    __shared__ float u_s[256];
    __shared__ __align__(16) float s_scale[512];
    __shared__ float part[64];
    __shared__ float swt[64];
    __shared__ float smx, sdn;
    const int tid = threadIdx.x, wid = tid >> 5, lane = tid & 31;
    const int wm = wid >> 2, wn = wid & 3;
    const int bt = blockIdx.x;
    const uint32_t aBase = smem_u32(sm);

    u_s[tid] = g_aq2[(size_t)bt * HD_ + tid] * Ws[tid];
    s_scale[tid]       = g_scale[(size_t)bt * VD_ + tid];
    s_scale[tid + 256] = g_scale[(size_t)bt * VD_ + tid + 256];
    if (tid < 64) part[tid] = 0.f;
    __syncthreads();

    float acc[2][8][4];
#pragma unroll
    for (int a = 0; a < 2; ++a)
#pragma unroll
        for (int b = 0; b < 8; ++b)
#pragma unroll
            for (int c = 0; c < 4; ++c) acc[a][b][c] = 0.f;

    gemm_mainloop_t<4>(acc, sm, aBase, video, s_scale,
                       g_W2h, g_W2l,
                       g_W2h + (size_t)16 * CHUNK_ELEMS,
                       g_W2l + (size_t)16 * CHUNK_ELEMS,
                       bt, tid, lane, wm, wn);

#pragma unroll
    for (int mt = 0; mt < 2; ++mt) {
        int r0 = wm * 32 + mt * 16 + (lane >> 2);
        float s0 = 0.f, s1 = 0.f;
#pragma unroll
        for (int nt = 0; nt < 8; ++nt) {
            int c0 = wn * 64 + nt * 8 + (lane & 3) * 2;
            float b0 = bv2[c0], b1 = bv2[c0 + 1];
            float u0 = u_s[c0], u1 = u_s[c0 + 1];
            s0 += fmaxf(acc[mt][nt][0] + b0, 0.f) * u0
                + fmaxf(acc[mt][nt][1] + b1, 0.f) * u1;
            s1 += fmaxf(acc[mt][nt][2] + b0, 0.f) * u0
                + fmaxf(acc[mt][nt][3] + b1, 0.f) * u1;
        }
        s0 += __shfl_xor_sync(0xffffffffu, s0, 1);
        s0 += __shfl_xor_sync(0xffffffffu, s0, 2);
        s1 += __shfl_xor_sync(0xffffffffu, s1, 1);
        s1 += __shfl_xor_sync(0xffffffffu, s1, 2);
        if ((lane & 3) == 0) {
            atomicAdd(&part[r0], s0);
            atomicAdd(&part[r0 + 8], s1);
        }
    }
    __syncthreads();

    if (tid < HW_) swt[tid] = tanhf(part[tid] + bs[0]);
    __syncthreads();
    if (tid == 0) {
        float mx = -1e30f;
        for (int h = 0; h < HW_; ++h) mx = fmaxf(mx, swt[h]);
        float den = 0.f;
        for (int h = 0; h < HW_; ++h) den += expf(swt[h] - mx);
        smx = mx; sdn = den;
    }
    __syncthreads();
    if (tid < HW_) swt[tid] = expf(swt[tid] - smx) / sdn;
    __syncthreads();

    for (int c = tid; c < VD_; c += 256) {
        float a = 0.f;
#pragma unroll 7
        for (int h = 0; h < HW_; ++h)
            a += swt[h] * video[((size_t)bt * HW_ + h) * VD_ + c];
        out[(size_t)bt * VD_ + c] = a * s_scale[c];
    }
}

// ---------------------------------------------------------------------------
// Launch
// ---------------------------------------------------------------------------
extern "C" void kernel_launch(void* const* d_in, const int* in_sizes, int n_in,
                              void* d_out, int out_size)
{
    const float* video = (const float*)d_in[0];
    const float* audio = (const float*)d_in[1];
    const float* Wv1   = (const float*)d_in[2];
    const float* bv1   = (const float*)d_in[3];
    const float* Wa1   = (const float*)d_in[4];
    const float* ba1   = (const float*)d_in[5];
    const float* Wb    = (const float*)d_in[6];
    const float* bb    = (const float*)d_in[7];
    const float* Wc    = (const float*)d_in[8];
    const float* bc    = (const float*)d_in[9];
    const float* Wv2   = (const float*)d_in[10];
    const float* bv2   = (const float*)d_in[11];
    const float* Wa2   = (const float*)d_in[12];
    const float* ba2   = (const float*)d_in[13];
    const float* Ws    = (const float*)d_in[14];
    const float* bs    = (const float*)d_in[15];
    float* out = (float*)d_out;

    cudaFuncSetAttribute(g1_mma, cudaFuncAttributeMaxDynamicSharedMemorySize, SMEM_G1);
    cudaFuncSetAttribute(g2_mma, cudaFuncAttributeMaxDynamicSharedMemorySize, SMEM_G2);

    k0_wconv<<<1536, 256>>>(Wv1, Wv2);
    kt_trans<<<256, 256>>>(Wb, Wc);
    k1_audio<<<BT_ / 32, 256>>>(audio, Wa1, ba1, Wa2, ba2);
    g1_mma<<<dim3(4, BT_), 256, SMEM_G1>>>(video, bv1);
    k3_catt<<<BT_ / 16, 256>>>(bb, bc);
    g2_mma<<<BT_, 256, SMEM_G2>>>(video, bv2, Ws, bs, out);
}